// round 1
// baseline (speedup 1.0000x reference)
#include <cuda_runtime.h>

#define PI_F 3.14159265358979f

// ---------------- device-global scratch (allocation-free) ----------------
__device__ float  d_style_ang[48];     // [b][i] = pi*tanh(style proj)
__device__ float  d_alpha0[6];         // layer-0 RY angle
__device__ float  d_cb0[6], d_sb0[6];  // cos/sin(beta0/2)
__device__ float2 d_g1[6][4];          // layer-1 combined RZ*RY 2x2 gates
__device__ float2 d_g2[6][4];          // measurement U3 2x2 gates
__device__ float  d_Wqs[64 * 64];      // Wq[s][c] = sum_i out_w[c,i]*sign_i(s)
__device__ float  d_phi[32768 * 6];    // per-pixel per-wire encoding angle

// ---------------- setup: tiny, one block ----------------
__global__ void k_setup(const float* __restrict__ style,
                        const float* __restrict__ sw, const float* __restrict__ sb,
                        const float* __restrict__ qcnn, const float* __restrict__ meas,
                        const float* __restrict__ ow) {
    int t = threadIdx.x;
    if (t < 48) {
        int bi = t / 6, i = t - bi * 6;
        float acc = sb[i];
        for (int k = 0; k < 128; k++) acc = fmaf(style[bi * 128 + k], sw[i * 128 + k], acc);
        d_style_ang[t] = PI_F * tanhf(acc);
    }
    if (t < 6) {
        int i = t;
        // qcnn shape (2,6,2,3): flat ((l*6+i)*2+r)*3 + 0
        float a0 = qcnn[(i * 2 + 0) * 3];
        float b0 = qcnn[(i * 2 + 1) * 3];
        d_alpha0[i] = a0;
        d_cb0[i] = cosf(0.5f * b0);
        d_sb0[i] = sinf(0.5f * b0);
        float a1 = qcnn[((6 + i) * 2 + 0) * 3];
        float b1 = qcnn[((6 + i) * 2 + 1) * 3];
        float ca = cosf(0.5f * a1), sa = sinf(0.5f * a1);
        float cb = cosf(0.5f * b1), sbv = sinf(0.5f * b1);
        // G = RZ(b1) * RY(a1)
        d_g1[i][0] = make_float2(cb * ca, -sbv * ca);
        d_g1[i][1] = make_float2(-cb * sa, sbv * sa);
        d_g1[i][2] = make_float2(cb * sa, sbv * sa);
        d_g1[i][3] = make_float2(cb * ca, sbv * ca);
        // U3(theta, phi, lam)
        float th = meas[i * 3 + 0], phv = meas[i * 3 + 1], la = meas[i * 3 + 2];
        float ct = cosf(0.5f * th), st = sinf(0.5f * th);
        d_g2[i][0] = make_float2(ct, 0.f);
        d_g2[i][1] = make_float2(-cosf(la) * st, -sinf(la) * st);
        d_g2[i][2] = make_float2(cosf(phv) * st, sinf(phv) * st);
        d_g2[i][3] = make_float2(cosf(phv + la) * ct, sinf(phv + la) * ct);
    }
    for (int idx = t; idx < 4096; idx += blockDim.x) {
        int s = idx >> 6, c = idx & 63;
        float acc = 0.f;
#pragma unroll
        for (int i = 0; i < 6; i++)
            acc += ow[c * 6 + i] * (((s >> (5 - i)) & 1) ? -1.f : 1.f);
        d_Wqs[idx] = acc;  // layout [s][c]
    }
}

// ---------------- fused conv (res 64ch + data 6ch) ----------------
// grid 256 blocks; block = 256 thr; tile = 4h x 32w pixels, 64 co.
// thread: pw = tid&31, cg = tid>>5; computes acc[4 ph][8 co], plus data ch cg (cg<6).
__global__ __launch_bounds__(256) void k_conv(
    const float* __restrict__ x, const float* __restrict__ wr,
    const float* __restrict__ rb, const float* __restrict__ wd,
    const float* __restrict__ db, float* __restrict__ out) {
    __shared__ float xs[8][6][34];
    __shared__ float ws[72][65];   // pad 65 to kill store bank conflicts
    __shared__ float wds[72][6];
    int blk = blockIdx.x;
    int b = blk >> 5;
    int ti = blk & 31;
    int h0 = (ti >> 1) << 2;
    int w0 = (ti & 1) << 5;
    int tid = threadIdx.x;
    int pw = tid & 31, cg = tid >> 5;

    float acc[4][8];
#pragma unroll
    for (int a = 0; a < 4; a++)
#pragma unroll
        for (int j = 0; j < 8; j++) acc[a][j] = 0.f;
    float accd[4] = {0.f, 0.f, 0.f, 0.f};

    const float* xb = x + b * 262144;

    for (int chunk = 0; chunk < 8; chunk++) {
        int ci0 = chunk << 3;
        __syncthreads();
        // x tile: 8 ci x 6 rows x 34 cols (halo + zero padding)
        for (int i = tid; i < 1632; i += 256) {
            int ci = i / 204; int rem = i - ci * 204;
            int r = rem / 34; int cpos = rem - r * 34;
            int gh = h0 - 1 + r, gw = w0 - 1 + cpos;
            float v = 0.f;
            if ((unsigned)gh < 64u && (unsigned)gw < 64u)
                v = xb[((ci0 + ci) << 12) + (gh << 6) + gw];
            xs[ci][r][cpos] = v;
        }
        // weights: contiguous 72-col slab per row, transposed into smem
        for (int i = tid; i < 4608; i += 256) {
            int c = i / 72, k = i - c * 72;
            ws[k][c] = wr[c * 576 + ci0 * 9 + k];
        }
        for (int i = tid; i < 432; i += 256) {
            int c = i / 72, k = i - c * 72;
            wds[k][c] = wd[c * 576 + ci0 * 9 + k];
        }
        __syncthreads();

        for (int cil = 0; cil < 8; cil++) {
#pragma unroll
            for (int kh = 0; kh < 3; kh++) {
#pragma unroll
                for (int kw = 0; kw < 3; kw++) {
                    int k = cil * 9 + kh * 3 + kw;
                    float xr[4];
#pragma unroll
                    for (int ph = 0; ph < 4; ph++) xr[ph] = xs[cil][kh + ph][kw + pw];
                    float wreg[8];
#pragma unroll
                    for (int j = 0; j < 8; j++) wreg[j] = ws[k][(cg << 3) + j];
#pragma unroll
                    for (int ph = 0; ph < 4; ph++)
#pragma unroll
                        for (int j = 0; j < 8; j++)
                            acc[ph][j] = fmaf(xr[ph], wreg[j], acc[ph][j]);
                    if (cg < 6) {
                        float wdv = wds[k][cg];
#pragma unroll
                        for (int ph = 0; ph < 4; ph++)
                            accd[ph] = fmaf(xr[ph], wdv, accd[ph]);
                    }
                }
            }
        }
    }

    // epilogue: residual conv + bias -> out
#pragma unroll
    for (int j = 0; j < 8; j++) {
        int co = (cg << 3) + j;
        float bias = rb[co];
#pragma unroll
        for (int ph = 0; ph < 4; ph++)
            out[((b * 64 + co) << 12) + ((h0 + ph) << 6) + w0 + pw] = acc[ph][j] + bias;
    }
    // data channel -> encoding angle phi
    if (cg < 6) {
        float sa_ = d_style_ang[b * 6 + cg] + d_alpha0[cg];
        float bias = db[cg];
#pragma unroll
        for (int ph = 0; ph < 4; ph++) {
            int p = (b << 12) + ((h0 + ph) << 6) + w0 + pw;
            d_phi[p * 6 + cg] = PI_F * tanhf(accd[ph] + bias) + sa_;
        }
    }
}

// ---------------- quantum sim: warp per pixel, 2 amps per lane ----------------
// state index s (6 bits): wire i <-> bit (5-i). slot0: s=lane, slot1: s=lane+32.
__device__ __forceinline__ void gate_b5(const float2* __restrict__ G,
                                        float& a0r, float& a0i, float& a1r, float& a1i) {
    float2 g00 = G[0], g01 = G[1], g10 = G[2], g11 = G[3];
    float n0r = g00.x * a0r - g00.y * a0i + g01.x * a1r - g01.y * a1i;
    float n0i = g00.x * a0i + g00.y * a0r + g01.x * a1i + g01.y * a1r;
    float n1r = g10.x * a0r - g10.y * a0i + g11.x * a1r - g11.y * a1i;
    float n1i = g10.x * a0i + g10.y * a0r + g11.x * a1i + g11.y * a1r;
    a0r = n0r; a0i = n0i; a1r = n1r; a1i = n1i;
}

__device__ __forceinline__ void gate_lo(int bbit, int lane, const float2* __restrict__ G,
                                        float& a0r, float& a0i, float& a1r, float& a1i) {
    const unsigned F = 0xffffffffu;
    float2 g00 = G[0], g01 = G[1], g10 = G[2], g11 = G[3];
    int m = 1 << bbit;
    float p0r = __shfl_xor_sync(F, a0r, m);
    float p0i = __shfl_xor_sync(F, a0i, m);
    float p1r = __shfl_xor_sync(F, a1r, m);
    float p1i = __shfl_xor_sync(F, a1i, m);
    bool hi = (lane >> bbit) & 1;
    float Ar = hi ? g11.x : g00.x, Ai = hi ? g11.y : g00.y;
    float Pr = hi ? g10.x : g01.x, Pi = hi ? g10.y : g01.y;
    float n0r = Ar * a0r - Ai * a0i + Pr * p0r - Pi * p0i;
    float n0i = Ar * a0i + Ai * a0r + Pr * p0i + Pi * p0r;
    float n1r = Ar * a1r - Ai * a1i + Pr * p1r - Pi * p1i;
    float n1i = Ar * a1i + Ai * a1r + Pr * p1i + Pi * p1r;
    a0r = n0r; a0i = n0i; a1r = n1r; a1i = n1i;
}

__device__ __forceinline__ void cnot_ring(int lane, float& a0r, float& a0i,
                                          float& a1r, float& a1i) {
    const unsigned F = 0xffffffffu;
    // CNOT(w0->w1): bits (5,4). slot-controlled: slot1 swaps bit4.
    a1r = __shfl_xor_sync(F, a1r, 16);
    a1i = __shfl_xor_sync(F, a1i, 16);
    // (4,3)
    { int src = lane ^ (((lane >> 4) & 1) << 3);
      a0r = __shfl_sync(F, a0r, src); a0i = __shfl_sync(F, a0i, src);
      a1r = __shfl_sync(F, a1r, src); a1i = __shfl_sync(F, a1i, src); }
    // (3,2)
    { int src = lane ^ (((lane >> 3) & 1) << 2);
      a0r = __shfl_sync(F, a0r, src); a0i = __shfl_sync(F, a0i, src);
      a1r = __shfl_sync(F, a1r, src); a1i = __shfl_sync(F, a1i, src); }
    // (2,1)
    { int src = lane ^ (((lane >> 2) & 1) << 1);
      a0r = __shfl_sync(F, a0r, src); a0i = __shfl_sync(F, a0i, src);
      a1r = __shfl_sync(F, a1r, src); a1i = __shfl_sync(F, a1i, src); }
    // (1,0)
    { int src = lane ^ ((lane >> 1) & 1);
      a0r = __shfl_sync(F, a0r, src); a0i = __shfl_sync(F, a0i, src);
      a1r = __shfl_sync(F, a1r, src); a1i = __shfl_sync(F, a1i, src); }
    // (0,5): control bit0, target slot bit -> conditional local slot swap
    { bool c = lane & 1;
      float t0r = c ? a1r : a0r, t0i = c ? a1i : a0i;
      float t1r = c ? a0r : a1r, t1i = c ? a0i : a1i;
      a0r = t0r; a0i = t0i; a1r = t1r; a1i = t1i; }
}

__global__ __launch_bounds__(256) void k_quant(const float* __restrict__ ob,
                                               float* __restrict__ out) {
    __shared__ float wq[64][64];   // [s][c]
    __shared__ float shp[8][64];
    __shared__ float sho[8][65];
    const unsigned F = 0xffffffffu;
    int tid = threadIdx.x;
    for (int i = tid; i < 4096; i += 256) wq[i >> 6][i & 63] = d_Wqs[i];
    __syncthreads();

    int warp = tid >> 5, lane = tid & 31;
    int p = (blockIdx.x << 3) + warp;

    float myphi = 0.f;
    if (lane < 6) myphi = d_phi[p * 6 + lane];

    // per-wire single-qubit states u_i = RZ(b0)RY(phi)|0>
    float u0r[6], u0i[6], u1r[6], u1i[6];
#pragma unroll
    for (int i = 0; i < 6; i++) {
        float ph = __shfl_sync(F, myphi, i);
        float sv, cv;
        __sincosf(0.5f * ph, &sv, &cv);
        float cb = d_cb0[i], sb = d_sb0[i];
        u0r[i] = cv * cb; u0i[i] = -cv * sb;
        u1r[i] = sv * cb; u1i[i] = sv * sb;
    }
    // product state
    float a0r = 1.f, a0i = 0.f, a1r, a1i;
#pragma unroll
    for (int i = 0; i < 6; i++) {
        int bit = (lane >> (5 - i)) & 1;  // slot0: bit5 of s == 0
        float ur = bit ? u1r[i] : u0r[i];
        float ui = bit ? u1i[i] : u0i[i];
        float nr = a0r * ur - a0i * ui;
        float ni = a0r * ui + a0i * ur;
        a0r = nr; a0i = ni;
    }
    a1r = u1r[0]; a1i = u1i[0];  // slot1: wire0 bit == 1
#pragma unroll
    for (int i = 1; i < 6; i++) {
        int bit = (lane >> (5 - i)) & 1;
        float ur = bit ? u1r[i] : u0r[i];
        float ui = bit ? u1i[i] : u0i[i];
        float nr = a1r * ur - a1i * ui;
        float ni = a1r * ui + a1i * ur;
        a1r = nr; a1i = ni;
    }

    cnot_ring(lane, a0r, a0i, a1r, a1i);
#pragma unroll
    for (int i = 0; i < 6; i++) {
        if (i == 0) gate_b5(d_g1[0], a0r, a0i, a1r, a1i);
        else        gate_lo(5 - i, lane, d_g1[i], a0r, a0i, a1r, a1i);
    }
    cnot_ring(lane, a0r, a0i, a1r, a1i);
#pragma unroll
    for (int i = 0; i < 6; i++) {
        if (i == 0) gate_b5(d_g2[0], a0r, a0i, a1r, a1i);
        else        gate_lo(5 - i, lane, d_g2[i], a0r, a0i, a1r, a1i);
    }

    // probabilities -> shared
    shp[warp][lane] = a0r * a0r + a0i * a0i;
    shp[warp][lane + 32] = a1r * a1r + a1i * a1i;
    __syncwarp();

    // out_q[c] = ob[c] + sum_s wq[s][c] * p[s]   (lane handles c=lane, lane+32)
    float o0 = ob[lane];
    float o1 = ob[lane + 32];
#pragma unroll 8
    for (int s = 0; s < 64; s++) {
        float pv = shp[warp][s];
        o0 = fmaf(wq[s][lane], pv, o0);
        o1 = fmaf(wq[s][lane + 32], pv, o1);
    }
    sho[warp][lane] = o0;
    sho[warp][lane + 32] = o1;
    __syncthreads();

    // coalesced-ish accumulate into out (8 consecutive pixels per c)
    int pbase = blockIdx.x << 3;
    int bb = pbase >> 12;
    int hw0 = pbase & 4095;
    for (int i = tid; i < 512; i += 256) {
        int c = i >> 3, pix = i & 7;
        int idx = ((bb * 64 + c) << 12) + hw0 + pix;
        out[idx] += sho[pix][c];
    }
}

// ---------------- launch ----------------
extern "C" void kernel_launch(void* const* d_in, const int* in_sizes, int n_in,
                              void* d_out, int out_size) {
    const float* x     = (const float*)d_in[0];
    const float* style = (const float*)d_in[1];
    const float* wd    = (const float*)d_in[2];   // data_proj_w [6,576]
    const float* db    = (const float*)d_in[3];   // data_proj_b [6]
    const float* sw    = (const float*)d_in[4];   // style_to_data_w [6,128]
    const float* sb    = (const float*)d_in[5];   // style_to_data_b [6]
    const float* qcnn  = (const float*)d_in[6];   // [2,6,2,3]
    const float* meas  = (const float*)d_in[7];   // [6,3]
    const float* ow    = (const float*)d_in[8];   // out_proj_w [64,6]
    const float* ob    = (const float*)d_in[9];   // out_proj_b [64]
    const float* wr    = (const float*)d_in[10];  // res_proj_w [64,576]
    const float* rb    = (const float*)d_in[11];  // res_proj_b [64]
    float* out = (float*)d_out;

    k_setup<<<1, 256>>>(style, sw, sb, qcnn, meas, ow);
    k_conv<<<256, 256>>>(x, wr, rb, wd, db, out);
    k_quant<<<4096, 256>>>(ob, out);
}